// round 8
// baseline (speedup 1.0000x reference)
#include <cuda_runtime.h>
#include <math.h>

// Shapes fixed by the problem: B=4, C=256, H=W=64, N=4096, Ci=128
#define B_  4
#define C_  256
#define N_  4096
#define CI_ 128

// Scratch (allocation-free rule: __device__ globals)
__device__ float g_xbar[B_ * C_];   // per-(b,c) spatial mean of x
__device__ float g_w[B_ * C_];      // w[b,c] = sum_k tbar[b,k] * phi_w[k,c]
__device__ float g_s[B_];           // s[b]  = sum_k tbar[b,k] * phi_b[k]
__device__ unsigned g_done;         // zero-init; reset by last block each run

// ---------------------------------------------------------------------------
// Kernel A: xbar[b,c] = mean_j x[b,c,j]  (1024 blocks x 256 thr, 1 row each),
// then the LAST block to finish runs the tiny matvec chain:
//   tbar[k] = theta_b[k] + sum_c theta_w[k,c]*xbar[b,c]
//   w[b,c]  = sum_k tbar[k]*phi_w[k,c];  s[b] = sum_k tbar[k]*phi_b[k]
// Blocks 0..7 prefetch the 256KB of weights into L2 so the tail matvec is
// L2-resident.
// ---------------------------------------------------------------------------
__global__ __launch_bounds__(256) void k_mean_w(
    const float* __restrict__ x,
    const float* __restrict__ theta_w, const float* __restrict__ theta_b,
    const float* __restrict__ phi_w,  const float* __restrict__ phi_b)
{
    const int tid  = threadIdx.x;
    const int lane = tid & 31, warp = tid >> 5;

    // L2 prefetch of weights: theta_w/phi_w are 128KB = 1024 lines each.
    if (blockIdx.x < 8) {
        const char* base = (blockIdx.x < 4) ? (const char*)theta_w
                                            : (const char*)phi_w;
        const char* p = base + ((size_t)(blockIdx.x & 3) * 256 + tid) * 128;
        asm volatile("prefetch.global.L2 [%0];" :: "l"(p));
    }

    // Row mean
    const int row = blockIdx.x;                 // b*C_ + c
    const float4* xr = (const float4*)(x + (size_t)row * N_);
    float acc = 0.f;
    #pragma unroll
    for (int i = 0; i < N_ / 4 / 256; ++i) {    // 4 independent float4 loads
        float4 v = xr[tid + i * 256];
        acc += v.x + v.y + v.z + v.w;
    }
    #pragma unroll
    for (int o = 16; o; o >>= 1) acc += __shfl_xor_sync(0xffffffffu, acc, o);
    __shared__ float warp_s[8];
    if (lane == 0) warp_s[warp] = acc;
    __syncthreads();
    if (tid == 0) {
        float s = 0.f;
        #pragma unroll
        for (int i = 0; i < 8; ++i) s += warp_s[i];
        g_xbar[row] = s * (1.0f / N_);
    }

    // Last-block-done: the 1024th block to arrive runs the matvec.
    __shared__ int is_last;
    __threadfence();                            // release g_xbar
    if (tid == 0) {
        unsigned old = atomicAdd(&g_done, 1u);
        is_last = (old == (unsigned)(gridDim.x - 1));
        if (is_last) g_done = 0u;               // reset for next graph replay
    }
    __syncthreads();
    if (!is_last) return;

    __shared__ float xb_s[C_];
    __shared__ float tb_s[CI_];
    for (int b = 0; b < B_; ++b) {
        xb_s[tid] = __ldcg(&g_xbar[b * C_ + tid]);
        __syncthreads();
        // tbar: 8 warps x 16 k, lane-parallel over c
        for (int i = 0; i < CI_ / 8; ++i) {
            const int k = warp * (CI_ / 8) + i;
            const float* tw = theta_w + (size_t)k * C_;
            float a = 0.f;
            #pragma unroll
            for (int c = lane; c < C_; c += 32) a += __ldg(tw + c) * xb_s[c];
            #pragma unroll
            for (int o = 16; o; o >>= 1) a += __shfl_xor_sync(0xffffffffu, a, o);
            if (lane == 0) tb_s[k] = a + __ldg(theta_b + k);
        }
        __syncthreads();
        float wacc = 0.f;
        #pragma unroll 8
        for (int k = 0; k < CI_; ++k)
            wacc += tb_s[k] * __ldg(phi_w + (size_t)k * C_ + tid);
        g_w[b * C_ + tid] = wacc;
        if (warp == 0) {
            float a = 0.f;
            #pragma unroll
            for (int k = lane; k < CI_; k += 32) a += tb_s[k] * __ldg(phi_b + k);
            #pragma unroll
            for (int o = 16; o; o >>= 1) a += __shfl_xor_sync(0xffffffffu, a, o);
            if (lane == 0) g_s[b] = a;
        }
        __syncthreads();                        // xb_s/tb_s reuse guard
    }
}

// ---------------------------------------------------------------------------
// Kernel B: fused dot + sigmoid + scale, x read once into registers.
// 1024 blocks x 128 threads = (16 pixels) x (8 splits of 32 channels).
// ~7 blocks/SM resident -> small tail imbalance. x is L2-hot from kernel A.
// ---------------------------------------------------------------------------
#define TJ_   16
#define CSPL_ 8
#define CPT_  32

__global__ __launch_bounds__(128, 8) void k_fused(const float* __restrict__ x,
                                                  float* __restrict__ out) {
    const int tid  = threadIdx.x;
    const int jloc = tid & (TJ_ - 1);
    const int csub = tid >> 4;                  // 0..7
    const int tile = blockIdx.x;                // 0..1023
    const int b    = tile >> 8;
    const int j    = (tile & 255) * TJ_ + jloc;

    __shared__ float ws[C_];
    __shared__ float part[CSPL_ * TJ_];
    __shared__ float conf_s[TJ_];
    __shared__ float sb_s;

    ws[tid]       = __ldcg(&g_w[b * C_ + tid]);
    ws[tid + 128] = __ldcg(&g_w[b * C_ + tid + 128]);
    if (tid == 0) sb_s = __ldcg(&g_s[b]);
    __syncthreads();

    const float* xb = x + (size_t)(b * C_) * N_ + j;
    float xv[CPT_];
    float acc = 0.f;
    #pragma unroll
    for (int i = 0; i < CPT_; ++i) {
        const int c = csub * CPT_ + i;
        xv[i] = __ldg(xb + (size_t)c * N_);
        acc += ws[c] * xv[i];
    }
    part[csub * TJ_ + jloc] = acc;
    __syncthreads();

    if (tid < TJ_) {
        float m = 0.f;
        #pragma unroll
        for (int k = 0; k < CSPL_; ++k) m += part[k * TJ_ + tid];
        m = (m + sb_s) * (1.0f / N_);
        conf_s[tid] = 1.0f / (1.0f + expf(-m));
    }
    __syncthreads();

    const float cf = conf_s[jloc];
    float* ob = out + (size_t)(b * C_) * N_ + j;
    #pragma unroll
    for (int i = 0; i < CPT_; ++i) {
        const int c = csub * CPT_ + i;
        ob[(size_t)c * N_] = cf * xv[i];
    }
}

// ---------------------------------------------------------------------------
extern "C" void kernel_launch(void* const* d_in, const int* in_sizes, int n_in,
                              void* d_out, int out_size) {
    const float* x       = (const float*)d_in[0];
    const float* theta_w = (const float*)d_in[1];
    const float* theta_b = (const float*)d_in[2];
    const float* phi_w   = (const float*)d_in[3];
    const float* phi_b   = (const float*)d_in[4];
    float* out = (float*)d_out;

    k_mean_w<<<B_ * C_, 256>>>(x, theta_w, theta_b, phi_w, phi_b);
    k_fused<<<1024, 128>>>(x, out);
}

// round 9
// speedup vs baseline: 2.8000x; 2.8000x over previous
#include <cuda_runtime.h>
#include <math.h>

// Shapes fixed by the problem: B=4, C=256, H=W=64, N=4096, Ci=128
#define B_  4
#define C_  256
#define N_  4096
#define CI_ 128

// Scratch (allocation-free rule: __device__ globals)
__device__ float g_xbar[B_ * C_];   // per-(b,c) spatial mean of x
__device__ float g_w[B_ * C_];      // w[b,c] = sum_k tbar[b,k] * phi_w[k,c]
__device__ float g_s[B_];           // s[b]  = sum_k tbar[b,k] * phi_b[k]

// ---------------------------------------------------------------------------
// Kernel 1: xbar. 512 blocks x 256 thr; each block reduces TWO rows so each
// thread front-batches 8 independent float4 loads (MLP=8).
// ---------------------------------------------------------------------------
__global__ __launch_bounds__(256) void k_rowmean(const float* __restrict__ x) {
    const int tid  = threadIdx.x;
    const int lane = tid & 31, warp = tid >> 5;
    const int row0 = blockIdx.x * 2;            // rows row0, row0+1

    const float4* xr0 = (const float4*)(x + (size_t)row0 * N_);
    const float4* xr1 = (const float4*)(x + (size_t)(row0 + 1) * N_);

    float4 v[8];
    #pragma unroll
    for (int i = 0; i < 4; ++i) v[i]     = xr0[tid + i * 256];
    #pragma unroll
    for (int i = 0; i < 4; ++i) v[4 + i] = xr1[tid + i * 256];

    float a0 = 0.f, a1 = 0.f;
    #pragma unroll
    for (int i = 0; i < 4; ++i) a0 += v[i].x + v[i].y + v[i].z + v[i].w;
    #pragma unroll
    for (int i = 0; i < 4; ++i) a1 += v[4+i].x + v[4+i].y + v[4+i].z + v[4+i].w;

    #pragma unroll
    for (int o = 16; o; o >>= 1) {
        a0 += __shfl_xor_sync(0xffffffffu, a0, o);
        a1 += __shfl_xor_sync(0xffffffffu, a1, o);
    }
    __shared__ float w0[8], w1[8];
    if (lane == 0) { w0[warp] = a0; w1[warp] = a1; }
    __syncthreads();
    if (tid == 0) {
        float s = 0.f;
        #pragma unroll
        for (int i = 0; i < 8; ++i) s += w0[i];
        g_xbar[row0] = s * (1.0f / N_);
    } else if (tid == 32) {
        float s = 0.f;
        #pragma unroll
        for (int i = 0; i < 8; ++i) s += w1[i];
        g_xbar[row0 + 1] = s * (1.0f / N_);
    }
}

// ---------------------------------------------------------------------------
// Kernel 2 (tiny): per batch b:
//   tbar[k] = theta_b[k] + sum_c theta_w[k,c] * xbar[b,c]
//   w[b,c]  = sum_k tbar[k] * phi_w[k,c];  s[b] = sum_k tbar[k] * phi_b[k]
// ---------------------------------------------------------------------------
__global__ __launch_bounds__(256) void k_small(const float* __restrict__ theta_w,
                                               const float* __restrict__ theta_b,
                                               const float* __restrict__ phi_w,
                                               const float* __restrict__ phi_b) {
    const int b = blockIdx.x;
    const int tid = threadIdx.x;
    const int warp = tid >> 5, lane = tid & 31;

    __shared__ float xb[C_];
    __shared__ float tb[CI_];

    xb[tid] = g_xbar[b * C_ + tid];
    __syncthreads();

    for (int i = 0; i < CI_ / 8; ++i) {
        int k = warp * (CI_ / 8) + i;
        const float* tw = theta_w + (size_t)k * C_;
        float a = 0.f;
        #pragma unroll
        for (int c = lane; c < C_; c += 32) a += tw[c] * xb[c];
        #pragma unroll
        for (int o = 16; o; o >>= 1) a += __shfl_xor_sync(0xffffffffu, a, o);
        if (lane == 0) tb[k] = a + theta_b[k];
    }
    __syncthreads();

    float wacc = 0.f;
    #pragma unroll 8
    for (int k = 0; k < CI_; ++k) wacc += tb[k] * phi_w[(size_t)k * C_ + tid];
    g_w[b * C_ + tid] = wacc;

    if (warp == 0) {
        float a = 0.f;
        #pragma unroll
        for (int k = lane; k < CI_; k += 32) a += tb[k] * phi_b[k];
        #pragma unroll
        for (int o = 16; o; o >>= 1) a += __shfl_xor_sync(0xffffffffu, a, o);
        if (lane == 0) g_s[b] = a;
    }
}

// ---------------------------------------------------------------------------
// Kernel 3: fused dot + sigmoid + scale, x read once into registers.
// 1024 blocks x 256 threads = (16 pixels) x (16 splits of 16 channels).
// xv[16] keeps regs ~40 -> 6 CTAs/SM via launch_bounds(256,6), occ ~75%.
// x is L2-hot from kernel 1; writes (16.8MB) are the DRAM-bound part.
// ---------------------------------------------------------------------------
#define TJ_   16
#define CSPL_ 16
#define CPT_  16

__global__ __launch_bounds__(256, 6) void k_fused(const float* __restrict__ x,
                                                  float* __restrict__ out) {
    const int tid  = threadIdx.x;
    const int jloc = tid & (TJ_ - 1);
    const int csub = tid >> 4;                  // 0..15
    const int tile = blockIdx.x;                // 0..1023
    const int b    = tile >> 8;
    const int j    = (tile & 255) * TJ_ + jloc;

    __shared__ float ws[C_];
    __shared__ float part[CSPL_ * TJ_];
    __shared__ float conf_s[TJ_];
    __shared__ float sb_s;

    ws[tid] = __ldcg(&g_w[b * C_ + tid]);
    if (tid == 0) sb_s = __ldcg(&g_s[b]);
    __syncthreads();

    const float* xb = x + (size_t)(b * C_) * N_ + j;
    float xv[CPT_];
    float acc = 0.f;
    #pragma unroll
    for (int i = 0; i < CPT_; ++i) {
        const int c = csub * CPT_ + i;
        xv[i] = __ldg(xb + (size_t)c * N_);
        acc += ws[c] * xv[i];
    }
    part[csub * TJ_ + jloc] = acc;
    __syncthreads();

    if (tid < TJ_) {
        float m = 0.f;
        #pragma unroll
        for (int k = 0; k < CSPL_; ++k) m += part[k * TJ_ + tid];
        m = (m + sb_s) * (1.0f / N_);
        conf_s[tid] = 1.0f / (1.0f + expf(-m));
    }
    __syncthreads();

    const float cf = conf_s[jloc];
    float* ob = out + (size_t)(b * C_) * N_ + j;
    #pragma unroll
    for (int i = 0; i < CPT_; ++i) {
        const int c = csub * CPT_ + i;
        ob[(size_t)c * N_] = cf * xv[i];
    }
}

// ---------------------------------------------------------------------------
extern "C" void kernel_launch(void* const* d_in, const int* in_sizes, int n_in,
                              void* d_out, int out_size) {
    const float* x       = (const float*)d_in[0];
    const float* theta_w = (const float*)d_in[1];
    const float* theta_b = (const float*)d_in[2];
    const float* phi_w   = (const float*)d_in[3];
    const float* phi_b   = (const float*)d_in[4];
    float* out = (float*)d_out;

    k_rowmean<<<B_ * C_ / 2, 256>>>(x);
    k_small<<<B_, 256>>>(theta_w, theta_b, phi_w, phi_b);
    k_fused<<<1024, 256>>>(x, out);
}